// round 15
// baseline (speedup 1.0000x reference)
#include <cuda_runtime.h>
#include <cuda_fp16.h>
#include <math.h>
#include <stdint.h>

// ---------------- constants ----------------
#define B_ROWS   16384
#define D_DIM    1024
#define KDIM     1024           // fp16 K
#define KU       512
#define NCAT     3584           // 1024(Wc1)+1024(Wr1)+1024(Wa)+512(Wo1)
#define ORD_H    512
#define N_EXP    7
#define MAX_TILES 136
#define MAX_SLOTS (MAX_TILES*128)
#define KITERS   32             // KDIM / 32
#define NSTAGE   5

// ---------------- scratch (float units) ----------------
#define OFF_DFH   0LL                      // Df fp16 [16384][1024]
#define OFF_X2    8388608LL                // X fp16 [16384][1024]
#define OFF_H12   16777216LL               // H1 fp16 [17408][1024]
#define OFF_WCAT  25690112LL               // Wcat fp16 [3584][1024]
#define OFF_WE1   27525120LL               // We1 fp16 [7][1024][1024]
#define OFF_WE2   31195136LL
#define OFF_BCAT  34865152LL               // bcat fp32 [3584]
#define OFF_LG    34868736LL               // Lg fp32 [16384][16]
#define TOTAL_F   35130880LL

__device__ __align__(1024) float g_buf[TOTAL_F];

__device__ int d_size_idx[B_ROWS];
__device__ int d_perm[MAX_SLOTS];
__device__ int d_tile_expert[MAX_TILES];
__device__ int d_count[N_EXP];
__device__ int d_cursor[N_EXP];
__device__ int d_off[N_EXP];
__device__ int d_fix_count;
__device__ int d_fix_rows[B_ROWS];

// ---------------- baseline-PTX helpers ----------------
__device__ __forceinline__ uint32_t smem_to_u32(const void* p) {
    uint32_t a;
    asm("{ .reg .u64 t; cvta.to.shared.u64 t, %1; cvt.u32.u64 %0, t; }" : "=r"(a) : "l"(p));
    return a;
}
#define CP_ASYNC16(dst, src) \
    asm volatile("cp.async.cg.shared.global [%0], [%1], 16;" :: "r"(dst), "l"(src))
#define CP_COMMIT() asm volatile("cp.async.commit_group;" ::: "memory")
#define CP_WAIT3()  asm volatile("cp.async.wait_group 3;" ::: "memory")

#define LDSM_X4(r0, r1, r2, r3, addr) \
    asm volatile("ldmatrix.sync.aligned.m8n8.x4.shared.b16 {%0,%1,%2,%3}, [%4];" \
        : "=r"(r0), "=r"(r1), "=r"(r2), "=r"(r3) : "r"(addr))

#define MMA_F16(d, a, b) \
    asm volatile("mma.sync.aligned.m16n8k16.row.col.f32.f16.f16.f32 " \
        "{%0,%1,%2,%3}, {%4,%5,%6,%7}, {%8,%9}, {%0,%1,%2,%3};" \
        : "+f"((d)[0]), "+f"((d)[1]), "+f"((d)[2]), "+f"((d)[3]) \
        : "r"((a)[0]), "r"((a)[1]), "r"((a)[2]), "r"((a)[3]), "r"((b)[0]), "r"((b)[1]))

__device__ __forceinline__ unsigned pack2(float a, float b) {
    const unsigned ha = (unsigned)__half_as_ushort(__float2half_rn(a));
    const unsigned hb = (unsigned)__half_as_ushort(__float2half_rn(b));
    return ha | (hb << 16);
}

// ---------------- conversions ----------------
__global__ void conv_f2h_kernel(const float* __restrict__ in, uint2* __restrict__ out)
{
    const size_t i = (size_t)blockIdx.x * 256 + threadIdx.x;
    const float4 v = reinterpret_cast<const float4*>(in)[i];
    out[i] = make_uint2(pack2(v.x, v.y), pack2(v.z, v.w));
}

// merged expert weight conversion: z<7 -> We1 expert z, z>=7 -> We2 expert z-7
__global__ void conv_we_kernel(const float* __restrict__ We1, const float* __restrict__ We2,
                               unsigned* __restrict__ o1, unsigned* __restrict__ o2)
{
    __shared__ float t[64][33];
    const int k0 = blockIdx.x * 64, n0 = blockIdx.y * 32;
    const int z = blockIdx.z;
    const int e = (z < N_EXP) ? z : z - N_EXP;
    const float* W   = ((z < N_EXP) ? We1 : We2) + (size_t)e * KDIM * D_DIM;
    unsigned*   out  = ((z < N_EXP) ? o1  : o2 ) + (size_t)e * D_DIM * KU;
    for (int r = threadIdx.y; r < 64; r += 8)
        t[r][threadIdx.x] = W[(size_t)(k0 + r) * D_DIM + n0 + threadIdx.x];
    __syncthreads();
    for (int r = threadIdx.y; r < 32; r += 8)
        out[(size_t)(n0 + r) * KU + k0 / 2 + threadIdx.x] =
            pack2(t[2 * threadIdx.x][r], t[2 * threadIdx.x + 1][r]);
}

// fused conversion of all four stage-1 weights into Wcat [3584][1024] fp16
__global__ void conv_wcat_kernel(const float* __restrict__ Wc1, const float* __restrict__ Wr1,
                                 const float* __restrict__ Wa, const float* __restrict__ Wo1,
                                 unsigned* __restrict__ out)
{
    __shared__ float t[64][33];
    const int k0 = blockIdx.x * 64;
    const int nc0 = blockIdx.y * 32;
    const float* W; int N; int nl;
    if (nc0 < 1024)      { W = Wc1; N = 1024; nl = nc0; }
    else if (nc0 < 2048) { W = Wr1; N = 1024; nl = nc0 - 1024; }
    else if (nc0 < 3072) { W = Wa;  N = 1024; nl = nc0 - 2048; }
    else                 { W = Wo1; N = 512;  nl = nc0 - 3072; }
    for (int r = threadIdx.y; r < 64; r += 8)
        t[r][threadIdx.x] = W[(size_t)(k0 + r) * N + nl + threadIdx.x];
    __syncthreads();
    for (int r = threadIdx.y; r < 32; r += 8)
        out[(size_t)(nc0 + r) * KU + k0 / 2 + threadIdx.x] =
            pack2(t[2 * threadIdx.x][r], t[2 * threadIdx.x + 1][r]);
}

// combined init: perm, counts, tile map, fix counter, bias concat, Lg zero
__global__ void init_kernel(const float* bc1, const float* br1,
                            const float* ba, const float* bo1,
                            float* bcat, float* Lg)
{
    const int i = blockIdx.x * blockDim.x + threadIdx.x;
    if (i < B_ROWS * 16) Lg[i] = 0.f;
    if (i < MAX_SLOTS) d_perm[i] = -1;
    if (i < N_EXP) { d_count[i] = 0; d_cursor[i] = 0; d_off[i] = 0; }
    if (i < MAX_TILES) d_tile_expert[i] = -1;
    if (i == 0) d_fix_count = 0;
    if (i < 1024)      bcat[i] = bc1[i];
    else if (i < 2048) bcat[i] = br1[i - 1024];
    else if (i < 3072) bcat[i] = ba[i - 2048];
    else if (i < 3584) bcat[i] = bo1[i - 3072];
}

// ---------------- HMMA GEMM with fused epilogues ----------------
// 512 threads / 16 warps (warp 32x32, 4x4 warp grid), tile 128x128, BK=32,
// 5-stage cp.async ring (r12 handshake).
// mode: 1 -> fp16-packed C
//       2 -> depth-fuse (relu(acc+b)·We3 atomically into out cols 21..23)
//       3 -> stage-1 fused: head tiles -> Lg atomics, Df tiles -> fp16 store
#define STAGE_B   20480
#define GSMEM_SZ  (STAGE_B * NSTAGE)      // 102400

__global__ __launch_bounds__(512, 2)
void gemm_hmma(const __half* __restrict__ A,
               const __half* __restrict__ Bw,
               const float* __restrict__ biasBase,
               void* __restrict__ Cv, int ldc, int lda,
               int useExpert, long long wStride, int biasStride,
               int mode, int gatherA,
               const float* __restrict__ We3,
               const float* __restrict__ Wc2,
               const float* __restrict__ Wr2,
               const float* __restrict__ Wo2,
               float* __restrict__ Lg)
{
    extern __shared__ __align__(128) unsigned char smem[];
    const int tileN = blockIdx.x, tileM = blockIdx.y;
    int e = 0;
    if (useExpert) { e = d_tile_expert[tileM]; if (e < 0) return; }

    const float* bias = biasBase + (size_t)e * biasStride;
    const __half* Bp = Bw + (size_t)e * wStride + (size_t)tileN * 128 * KDIM;

    const uint32_t sbase = smem_to_u32(smem);
    const int tid = threadIdx.x, wid = tid >> 5, lane = tid & 31;
    const int wm = wid >> 2, wn = wid & 3;          // 4 x 4 warp grid (32x32 tiles)
    const int lrow = lane & 15, lcol = lane >> 4;

    const int rc = tid >> 2, sg = tid & 3;          // cp.async: 1 A + 1 B chunk/thread

    int row0 = tileM * 128 + rc;
    if (gatherA) {
        const int p0 = d_perm[row0]; row0 = (p0 < 0) ? 0 : p0;
    }
    const __half* A0 = A + (size_t)row0 * lda;

    auto issue = [&](int kt, int stage) {
        const uint32_t base = sbase + stage * STAGE_B;
        const int k0 = kt * 32;
        CP_ASYNC16(base + rc * 80 + sg * 16,         A0 + k0 + sg * 8);
        CP_ASYNC16(base + 10240 + rc * 80 + sg * 16, Bp + (size_t)rc * KDIM + k0 + sg * 8);
    };

    float acc[2][4][4] = {};

    issue(0, 0); CP_COMMIT();
    issue(1, 1); CP_COMMIT();
    issue(2, 2); CP_COMMIT();
    issue(3, 3); CP_COMMIT();

    int sc = 0, si = 4;
    for (int kt = 0; kt < KITERS; kt++) {
        CP_WAIT3();
        __syncthreads();
        if (kt + 4 < KITERS) issue(kt + 4, si);
        CP_COMMIT();

        const uint32_t ab = sbase + sc * STAGE_B;
        const uint32_t bb = ab + 10240;
        #pragma unroll
        for (int kk = 0; kk < 2; kk++) {
            uint32_t a[2][4];
            #pragma unroll
            for (int i = 0; i < 2; i++) {
                const uint32_t addr = ab + (wm * 32 + i * 16 + lrow) * 80 + (kk * 16 + lcol * 8) * 2;
                LDSM_X4(a[i][0], a[i][1], a[i][2], a[i][3], addr);
            }
            uint32_t b[4][2];
            #pragma unroll
            for (int j4 = 0; j4 < 2; j4++) {
                uint32_t q0, q1, q2, q3;
                const uint32_t addr = bb + (wn * 32 + j4 * 16 + lrow) * 80 + (kk * 16 + lcol * 8) * 2;
                LDSM_X4(q0, q1, q2, q3, addr);
                b[2 * j4][0] = q0;     b[2 * j4][1] = q2;
                b[2 * j4 + 1][0] = q1; b[2 * j4 + 1][1] = q3;
            }
            #pragma unroll
            for (int i = 0; i < 2; i++)
                #pragma unroll
                for (int j = 0; j < 4; j++)
                    MMA_F16(acc[i][j], a[i], b[j]);
        }
        sc = (sc + 1 == NSTAGE) ? 0 : sc + 1;
        si = (si + 1 == NSTAGE) ? 0 : si + 1;
    }

    const int rbase = tileM * 128 + wm * 32 + (lane >> 2);
    const int cbase = tileN * 128 + wn * 32 + (lane & 3) * 2;
    static const int roff[4] = {0, 8, 16, 24};

    const bool df_store = (mode == 3) && (tileN >= 16 && tileN < 24);
    if (mode == 1 || df_store) {
        unsigned* C16 = (unsigned*)Cv;
        const int ldu = ldc >> 1;
        const int creb = df_store ? 2048 : 0;
        #pragma unroll
        for (int j = 0; j < 4; j++) {
            const int col = cbase + j * 8;
            const float2 bz = *reinterpret_cast<const float2*>(bias + col);
            const int cl = col - creb;
            #pragma unroll
            for (int i = 0; i < 2; i++) {
                const int ra = rbase + i * 16;
                C16[(size_t)ra * ldu + (cl >> 1)] =
                    pack2(fmaxf(acc[i][j][0] + bz.x, 0.f), fmaxf(acc[i][j][1] + bz.y, 0.f));
                C16[(size_t)(ra + 8) * ldu + (cl >> 1)] =
                    pack2(fmaxf(acc[i][j][2] + bz.x, 0.f), fmaxf(acc[i][j][3] + bz.y, 0.f));
            }
        }
    } else if (mode == 3) {
        int nOut, lgoff, creg;
        const float* W2;
        if (tileN < 8)       { nOut = 7; W2 = Wc2; lgoff = 0; creg = 0; }
        else if (tileN < 16) { nOut = 1; W2 = Wr2; lgoff = 7; creg = 1024; }
        else                 { nOut = 6; W2 = Wo2; lgoff = 8; creg = 3072; }
        float s[4][7];
        #pragma unroll
        for (int rp = 0; rp < 4; rp++)
            #pragma unroll
            for (int c = 0; c < 7; c++) s[rp][c] = 0.f;
        #pragma unroll
        for (int j = 0; j < 4; j++) {
            const int col = cbase + j * 8;
            const float2 bz = *reinterpret_cast<const float2*>(bias + col);
            const int cl = col - creg;
            #pragma unroll
            for (int c = 0; c < 7; c++) {
                if (c < nOut) {
                    const float w0 = W2[(size_t)cl * nOut + c];
                    const float w1 = W2[(size_t)(cl + 1) * nOut + c];
                    #pragma unroll
                    for (int i = 0; i < 2; i++) {
                        const float v0 = fmaxf(acc[i][j][0] + bz.x, 0.f);
                        const float v1 = fmaxf(acc[i][j][1] + bz.y, 0.f);
                        const float v2 = fmaxf(acc[i][j][2] + bz.x, 0.f);
                        const float v3 = fmaxf(acc[i][j][3] + bz.y, 0.f);
                        s[i * 2 + 0][c] += v0 * w0 + v1 * w1;
                        s[i * 2 + 1][c] += v2 * w0 + v3 * w1;
                    }
                }
            }
        }
        #pragma unroll
        for (int off = 1; off <= 2; off <<= 1)
            #pragma unroll
            for (int rp = 0; rp < 4; rp++)
                #pragma unroll
                for (int c = 0; c < 7; c++)
                    s[rp][c] += __shfl_xor_sync(0xffffffffu, s[rp][c], off);
        if ((lane & 3) == 0) {
            #pragma unroll
            for (int rp = 0; rp < 4; rp++) {
                const int row = rbase + roff[rp];
                #pragma unroll
                for (int c = 0; c < 7; c++)
                    if (c < nOut) atomicAdd(&Lg[(size_t)row * 16 + lgoff + c], s[rp][c]);
            }
        }
    } else {
        const float* w3 = We3 + (size_t)e * D_DIM * 3;
        float s[4][3] = {};
        #pragma unroll
        for (int j = 0; j < 4; j++) {
            const int col = cbase + j * 8;
            const float2 bz = *reinterpret_cast<const float2*>(bias + col);
            const float w00 = w3[col * 3 + 0], w01 = w3[col * 3 + 1], w02 = w3[col * 3 + 2];
            const float w10 = w3[col * 3 + 3], w11 = w3[col * 3 + 4], w12 = w3[col * 3 + 5];
            #pragma unroll
            for (int i = 0; i < 2; i++) {
                const float v0 = fmaxf(acc[i][j][0] + bz.x, 0.f);
                const float v1 = fmaxf(acc[i][j][1] + bz.y, 0.f);
                const float v2 = fmaxf(acc[i][j][2] + bz.x, 0.f);
                const float v3 = fmaxf(acc[i][j][3] + bz.y, 0.f);
                s[i * 2 + 0][0] += v0 * w00 + v1 * w10;
                s[i * 2 + 0][1] += v0 * w01 + v1 * w11;
                s[i * 2 + 0][2] += v0 * w02 + v1 * w12;
                s[i * 2 + 1][0] += v2 * w00 + v3 * w10;
                s[i * 2 + 1][1] += v2 * w01 + v3 * w11;
                s[i * 2 + 1][2] += v2 * w02 + v3 * w12;
            }
        }
        #pragma unroll
        for (int off = 1; off <= 2; off <<= 1)
            #pragma unroll
            for (int rp = 0; rp < 4; rp++)
                #pragma unroll
                for (int t = 0; t < 3; t++)
                    s[rp][t] += __shfl_xor_sync(0xffffffffu, s[rp][t], off);
        if ((lane & 3) == 0) {
            float* out = (float*)Cv;
            #pragma unroll
            for (int rp = 0; rp < 4; rp++) {
                const int slot = rbase + roff[rp];
                const int p = d_perm[slot];
                if (p >= 0) {
                    atomicAdd(&out[(size_t)p * 24 + 21], s[rp][0]);
                    atomicAdd(&out[(size_t)p * 24 + 22], s[rp][1]);
                    atomicAdd(&out[(size_t)p * 24 + 23], s[rp][2]);
                }
            }
        }
    }
}

// ---------------- head finalize (1 thread/row) ----------------
__global__ void head2_kernel(const float* __restrict__ Lg,
                             const float* __restrict__ bc2, const float* __restrict__ bo2,
                             const float* __restrict__ br2, const float* __restrict__ be3,
                             float* __restrict__ out)
{
    const int row = blockIdx.x * blockDim.x + threadIdx.x;
    if (row >= B_ROWS) return;
    const float* lg = Lg + (size_t)row * 16;

    float sl[7];
    #pragma unroll
    for (int c = 0; c < 7; c++) sl[c] = lg[c] + bc2[c];
    float mx = sl[0];
    #pragma unroll
    for (int c = 1; c < 7; c++) mx = fmaxf(mx, sl[c]);
    float ex[7], ssum = 0.f;
    #pragma unroll
    for (int c = 0; c < 7; c++) { ex[c] = expf(sl[c] - mx); ssum += ex[c]; }
    const float inv = 1.f / ssum;

    float expected = 0.f;
    int idx = 0; float best = sl[0], best2 = -1e30f;
    float* orow = out + (size_t)row * 24;
    #pragma unroll
    for (int c = 0; c < 7; c++) {
        const float p = ex[c] * inv;
        expected = fmaf(p, (float)c * (1.0f / 6.0f), expected);
        orow[c] = sl[c];
        orow[14 + c] = p;
        if (c > 0) {
            if (sl[c] > best) { best2 = best; best = sl[c]; idx = c; }
            else if (sl[c] > best2) best2 = sl[c];
        }
    }
    #pragma unroll
    for (int c = 0; c < 6; c++) orow[7 + c] = lg[8 + c] + bo2[c];
    const float resid = 0.35f * tanhf(lg[7] + br2[0]);
    orow[13] = fminf(fmaxf(expected + resid, 0.f), 1.f);
    orow[21] = be3[idx * 3 + 0];
    orow[22] = be3[idx * 3 + 1];
    orow[23] = be3[idx * 3 + 2];
    d_size_idx[row] = idx;
    atomicAdd(&d_count[idx], 1);
    if (best - best2 < 4e-3f) {
        int p = atomicAdd(&d_fix_count, 1);
        if (p < B_ROWS) d_fix_rows[p] = row;
    }
}

// exact fp32 argmax recompute for near-tie rows
__global__ void fix_kernel(const float* __restrict__ x,
                           const float* __restrict__ Wc1, const float* __restrict__ bc1,
                           const float* __restrict__ Wc2, const float* __restrict__ bc2,
                           const float* __restrict__ be3,
                           float* __restrict__ out)
{
    __shared__ float xr[D_DIM];
    __shared__ float h[D_DIM];
    __shared__ float lg[8];
    int n = d_fix_count; if (n > B_ROWS) n = B_ROWS;
    for (int i = blockIdx.x; i < n; i += gridDim.x) {
        const int row = d_fix_rows[i];
        for (int k = threadIdx.x; k < D_DIM; k += 256) xr[k] = x[(size_t)row * D_DIM + k];
        __syncthreads();
        for (int j = threadIdx.x; j < D_DIM; j += 256) {
            float s = bc1[j];
            for (int k = 0; k < D_DIM; k++) s = fmaf(xr[k], Wc1[(size_t)k * D_DIM + j], s);
            h[j] = fmaxf(s, 0.f);
        }
        __syncthreads();
        const int w = threadIdx.x >> 5, l = threadIdx.x & 31;
        if (w < 7) {
            float s = 0.f;
            for (int k = l; k < D_DIM; k += 32) s = fmaf(h[k], Wc2[k * 7 + w], s);
            #pragma unroll
            for (int off = 16; off; off >>= 1) s += __shfl_xor_sync(0xffffffffu, s, off);
            if (!l) lg[w] = s + bc2[w];
        }
        __syncthreads();
        if (threadIdx.x == 0) {
            int idx = 0; float best = lg[0];
            #pragma unroll
            for (int c = 1; c < 7; c++) if (lg[c] > best) { best = lg[c]; idx = c; }
            const int old = d_size_idx[row];
            if (idx != old) {
                atomicSub(&d_count[old], 1);
                atomicAdd(&d_count[idx], 1);
                d_size_idx[row] = idx;
                float* orow = out + (size_t)row * 24;
                orow[21] = be3[idx * 3 + 0];
                orow[22] = be3[idx * 3 + 1];
                orow[23] = be3[idx * 3 + 2];
            }
        }
        __syncthreads();
    }
}

// ---------------- routing scan + scatter ----------------
__global__ void scan_kernel()
{
    int off = 0;
    for (int e = 0; e < N_EXP; e++) {
        d_off[e] = off;
        const int tiles = (d_count[e] + 127) >> 7;
        const int base = off >> 7;
        for (int t = 0; t < tiles; t++) d_tile_expert[base + t] = e;
        off += tiles << 7;
    }
}
__global__ void scatter_kernel()
{
    const int r = blockIdx.x * blockDim.x + threadIdx.x;
    if (r < B_ROWS) {
        const int e = d_size_idx[r];
        const int pos = d_off[e] + atomicAdd(&d_cursor[e], 1);
        d_perm[pos] = r;
    }
}

// ---------------- launch ----------------
extern "C" void kernel_launch(void* const* d_in, const int* in_sizes, int n_in,
                              void* d_out, int out_size)
{
    const float* x   = (const float*)d_in[0];
    const float* Wc1 = (const float*)d_in[1];
    const float* bc1 = (const float*)d_in[2];
    const float* Wc2 = (const float*)d_in[3];
    const float* bc2 = (const float*)d_in[4];
    const float* Wo1 = (const float*)d_in[5];
    const float* bo1 = (const float*)d_in[6];
    const float* Wo2 = (const float*)d_in[7];
    const float* bo2 = (const float*)d_in[8];
    const float* Wr1 = (const float*)d_in[9];
    const float* br1 = (const float*)d_in[10];
    const float* Wr2 = (const float*)d_in[11];
    const float* br2 = (const float*)d_in[12];
    const float* Wa  = (const float*)d_in[13];
    const float* ba  = (const float*)d_in[14];
    const float* We1 = (const float*)d_in[15];
    const float* be1 = (const float*)d_in[16];
    const float* We2 = (const float*)d_in[17];
    const float* be2 = (const float*)d_in[18];
    const float* We3 = (const float*)d_in[19];
    const float* be3 = (const float*)d_in[20];
    float* out = (float*)d_out;

    float* buf = nullptr;
    cudaGetSymbolAddress((void**)&buf, g_buf);
    __half*   Dfh  = (__half*)(buf + OFF_DFH);
    unsigned* X2   = (unsigned*)(buf + OFF_X2);
    unsigned* H12  = (unsigned*)(buf + OFF_H12);
    unsigned* Wcat = (unsigned*)(buf + OFF_WCAT);
    unsigned* W2e1 = (unsigned*)(buf + OFF_WE1);
    unsigned* W2e2 = (unsigned*)(buf + OFF_WE2);
    float*    bcat = buf + OFF_BCAT;
    float*    Lg   = buf + OFF_LG;

    cudaFuncSetAttribute(gemm_hmma, cudaFuncAttributeMaxDynamicSharedMemorySize, GSMEM_SZ);

    // 1-3: conversions + init (gemm1 at launch #4 for ncu visibility)
    conv_f2h_kernel<<<B_ROWS, 256>>>(x, (uint2*)X2);
    conv_wcat_kernel<<<dim3(16, 112), dim3(32, 8)>>>(Wc1, Wr1, Wa, Wo1, Wcat);
    init_kernel<<<(B_ROWS * 16 + 255) / 256, 256>>>(bc1, br1, ba, bo1, bcat, Lg);

    // 4: fused stage-1 GEMM: head dots -> Lg (atomics), Df -> fp16 Dfh
    gemm_hmma<<<dim3(NCAT / 128, B_ROWS / 128), 512, GSMEM_SZ>>>(
        (const __half*)X2, (const __half*)Wcat, bcat, Dfh, D_DIM, KDIM,
        0, 0, 0, 3, 0, nullptr, Wc2, Wr2, Wo2, Lg);

    // 5: merged expert weight conversion (We1 + We2, one launch)
    conv_we_kernel<<<dim3(16, 32, 2 * N_EXP), dim3(32, 8)>>>(We1, We2, W2e1, W2e2);

    // 6-9: head finalize + near-tie fixup + routing tables
    head2_kernel<<<(B_ROWS + 255) / 256, 256>>>(Lg, bc2, bo2, br2, be3, out);
    fix_kernel<<<64, 256>>>(x, Wc1, bc1, Wc2, bc2, be3, out);
    scan_kernel<<<1, 1>>>();
    scatter_kernel<<<(B_ROWS + 255) / 256, 256>>>();

    // 10-11: expert MLP (gemm2 gathers rows from dense Dfh; gemm3 depth-fused)
    gemm_hmma<<<dim3(8, MAX_TILES), 512, GSMEM_SZ>>>(
        (const __half*)Dfh, (const __half*)W2e1, be1, H12, D_DIM, D_DIM,
        1, (long long)D_DIM * KDIM, D_DIM, 1, 1, nullptr, nullptr, nullptr, nullptr, nullptr);
    gemm_hmma<<<dim3(8, MAX_TILES), 512, GSMEM_SZ>>>(
        (const __half*)H12, (const __half*)W2e2, be2, out, 24, KDIM,
        1, (long long)D_DIM * KDIM, D_DIM, 2, 0, We3, nullptr, nullptr, nullptr, nullptr);
}

// round 16
// speedup vs baseline: 1.0403x; 1.0403x over previous
#include <cuda_runtime.h>
#include <cuda_fp16.h>
#include <math.h>
#include <stdint.h>

// ---------------- constants ----------------
#define B_ROWS   16384
#define D_DIM    1024
#define KDIM     1024           // fp16 K
#define KU       512
#define NCAT     3584           // 1024(Wc1)+1024(Wr1)+1024(Wa)+512(Wo1)
#define ORD_H    512
#define N_EXP    7
#define MAX_TILES 136
#define MAX_SLOTS (MAX_TILES*128)
#define KITERS   32             // KDIM / 32
#define NSTAGE   5

// ---------------- scratch (float units) ----------------
#define OFF_DFH   0LL                      // Df fp16 [16384][1024]
#define OFF_X2    8388608LL                // X fp16 [16384][1024]
#define OFF_H12   16777216LL               // H1 fp16 [17408][1024]
#define OFF_WCAT  25690112LL               // Wcat fp16 [3584][1024]
#define OFF_WE1   27525120LL               // We1 fp16 [7][1024][1024]
#define OFF_WE2   31195136LL
#define OFF_BCAT  34865152LL               // bcat fp32 [3584]
#define OFF_LG    34868736LL               // Lg fp32 [16384][16]
#define TOTAL_F   35130880LL

__device__ __align__(1024) float g_buf[TOTAL_F];

__device__ int d_size_idx[B_ROWS];
__device__ int d_perm[MAX_SLOTS];
__device__ int d_tile_expert[MAX_TILES];
__device__ int d_count[N_EXP];
__device__ int d_cursor[N_EXP];
__device__ int d_off[N_EXP];
__device__ int d_fix_count;
__device__ int d_fix_rows[B_ROWS];

// ---------------- baseline-PTX helpers ----------------
__device__ __forceinline__ uint32_t smem_to_u32(const void* p) {
    uint32_t a;
    asm("{ .reg .u64 t; cvta.to.shared.u64 t, %1; cvt.u32.u64 %0, t; }" : "=r"(a) : "l"(p));
    return a;
}
#define CP_ASYNC16(dst, src) \
    asm volatile("cp.async.cg.shared.global [%0], [%1], 16;" :: "r"(dst), "l"(src))
#define CP_COMMIT() asm volatile("cp.async.commit_group;" ::: "memory")
#define CP_WAIT3()  asm volatile("cp.async.wait_group 3;" ::: "memory")

#define LDSM_X4(r0, r1, r2, r3, addr) \
    asm volatile("ldmatrix.sync.aligned.m8n8.x4.shared.b16 {%0,%1,%2,%3}, [%4];" \
        : "=r"(r0), "=r"(r1), "=r"(r2), "=r"(r3) : "r"(addr))

#define MMA_F16(d, a, b) \
    asm volatile("mma.sync.aligned.m16n8k16.row.col.f32.f16.f16.f32 " \
        "{%0,%1,%2,%3}, {%4,%5,%6,%7}, {%8,%9}, {%0,%1,%2,%3};" \
        : "+f"((d)[0]), "+f"((d)[1]), "+f"((d)[2]), "+f"((d)[3]) \
        : "r"((a)[0]), "r"((a)[1]), "r"((a)[2]), "r"((a)[3]), "r"((b)[0]), "r"((b)[1]))

__device__ __forceinline__ unsigned pack2(float a, float b) {
    const unsigned ha = (unsigned)__half_as_ushort(__float2half_rn(a));
    const unsigned hb = (unsigned)__half_as_ushort(__float2half_rn(b));
    return ha | (hb << 16);
}

// ---------------- conversions ----------------
// x fp32 -> fp16 rows, FUSED with routing/bias/Lg init (grid covers init range)
__global__ void conv_x_init_kernel(const float* __restrict__ in, uint2* __restrict__ out,
                                   const float* bc1, const float* br1,
                                   const float* ba, const float* bo1,
                                   float* bcat, float* Lg)
{
    const size_t i = (size_t)blockIdx.x * 256 + threadIdx.x;
    const float4 v = reinterpret_cast<const float4*>(in)[i];
    out[i] = make_uint2(pack2(v.x, v.y), pack2(v.z, v.w));

    // init work (index range strictly below grid size)
    if (i < (size_t)B_ROWS * 16) Lg[i] = 0.f;
    if (i < MAX_SLOTS) d_perm[i] = -1;
    if (i < N_EXP) { d_count[i] = 0; d_cursor[i] = 0; d_off[i] = 0; }
    if (i < MAX_TILES) d_tile_expert[i] = -1;
    if (i == 0) d_fix_count = 0;
    if (i < 1024)      bcat[i] = bc1[i];
    else if (i < 2048) bcat[i] = br1[i - 1024];
    else if (i < 3072) bcat[i] = ba[i - 2048];
    else if (i < 3584) bcat[i] = bo1[i - 3072];
}

// merged expert weight conversion: z<7 -> We1 expert z, z>=7 -> We2 expert z-7
__global__ void conv_we_kernel(const float* __restrict__ We1, const float* __restrict__ We2,
                               unsigned* __restrict__ o1, unsigned* __restrict__ o2)
{
    __shared__ float t[64][33];
    const int k0 = blockIdx.x * 64, n0 = blockIdx.y * 32;
    const int z = blockIdx.z;
    const int e = (z < N_EXP) ? z : z - N_EXP;
    const float* W   = ((z < N_EXP) ? We1 : We2) + (size_t)e * KDIM * D_DIM;
    unsigned*   out  = ((z < N_EXP) ? o1  : o2 ) + (size_t)e * D_DIM * KU;
    for (int r = threadIdx.y; r < 64; r += 8)
        t[r][threadIdx.x] = W[(size_t)(k0 + r) * D_DIM + n0 + threadIdx.x];
    __syncthreads();
    for (int r = threadIdx.y; r < 32; r += 8)
        out[(size_t)(n0 + r) * KU + k0 / 2 + threadIdx.x] =
            pack2(t[2 * threadIdx.x][r], t[2 * threadIdx.x + 1][r]);
}

// fused conversion of all four stage-1 weights into Wcat [3584][1024] fp16
__global__ void conv_wcat_kernel(const float* __restrict__ Wc1, const float* __restrict__ Wr1,
                                 const float* __restrict__ Wa, const float* __restrict__ Wo1,
                                 unsigned* __restrict__ out)
{
    __shared__ float t[64][33];
    const int k0 = blockIdx.x * 64;
    const int nc0 = blockIdx.y * 32;
    const float* W; int N; int nl;
    if (nc0 < 1024)      { W = Wc1; N = 1024; nl = nc0; }
    else if (nc0 < 2048) { W = Wr1; N = 1024; nl = nc0 - 1024; }
    else if (nc0 < 3072) { W = Wa;  N = 1024; nl = nc0 - 2048; }
    else                 { W = Wo1; N = 512;  nl = nc0 - 3072; }
    for (int r = threadIdx.y; r < 64; r += 8)
        t[r][threadIdx.x] = W[(size_t)(k0 + r) * N + nl + threadIdx.x];
    __syncthreads();
    for (int r = threadIdx.y; r < 32; r += 8)
        out[(size_t)(nc0 + r) * KU + k0 / 2 + threadIdx.x] =
            pack2(t[2 * threadIdx.x][r], t[2 * threadIdx.x + 1][r]);
}

// ---------------- HMMA GEMM with fused epilogues (r12 pipeline, UNCHANGED) ----------------
// 256 threads / 8 warps (warp 32x64), tile 128x128, BK=32, 5-stage cp.async ring
// mode: 1 -> fp16-packed C
//       2 -> depth-fuse (relu(acc+b)·We3 atomically into out cols 21..23)
//       3 -> stage-1 fused: head tiles -> Lg atomics, Df tiles -> fp16 store
#define STAGE_B   20480
#define GSMEM_SZ  (STAGE_B * NSTAGE)      // 102400

__global__ __launch_bounds__(256, 2)
void gemm_hmma(const __half* __restrict__ A,
               const __half* __restrict__ Bw,
               const float* __restrict__ biasBase,
               void* __restrict__ Cv, int ldc, int lda,
               int useExpert, long long wStride, int biasStride,
               int mode, int gatherA,
               const float* __restrict__ We3,
               const float* __restrict__ Wc2,
               const float* __restrict__ Wr2,
               const float* __restrict__ Wo2,
               float* __restrict__ Lg)
{
    extern __shared__ __align__(128) unsigned char smem[];
    const int tileN = blockIdx.x, tileM = blockIdx.y;
    int e = 0;
    if (useExpert) { e = d_tile_expert[tileM]; if (e < 0) return; }

    const float* bias = biasBase + (size_t)e * biasStride;
    const __half* Bp = Bw + (size_t)e * wStride + (size_t)tileN * 128 * KDIM;

    const uint32_t sbase = smem_to_u32(smem);
    const int tid = threadIdx.x, wid = tid >> 5, lane = tid & 31;
    const int wm = wid >> 1, wn = wid & 1;
    const int lrow = lane & 15, lcol = lane >> 4;

    const int r0c = tid >> 2, s0c = tid & 3;
    const int r1c = 64 + (tid >> 2), s1c = tid & 3;

    int row0 = tileM * 128 + r0c, row1 = tileM * 128 + r1c;
    if (gatherA) {
        const int p0 = d_perm[row0]; row0 = (p0 < 0) ? 0 : p0;
        const int p1 = d_perm[row1]; row1 = (p1 < 0) ? 0 : p1;
    }
    const __half* A0 = A + (size_t)row0 * lda;
    const __half* A1 = A + (size_t)row1 * lda;

    auto issue = [&](int kt, int stage) {
        const uint32_t base = sbase + stage * STAGE_B;
        const int k0 = kt * 32;
        CP_ASYNC16(base + r0c * 80 + s0c * 16,         A0 + k0 + s0c * 8);
        CP_ASYNC16(base + r1c * 80 + s1c * 16,         A1 + k0 + s1c * 8);
        CP_ASYNC16(base + 10240 + r0c * 80 + s0c * 16, Bp + (size_t)r0c * KDIM + k0 + s0c * 8);
        CP_ASYNC16(base + 10240 + r1c * 80 + s1c * 16, Bp + (size_t)r1c * KDIM + k0 + s1c * 8);
    };

    float acc[2][8][4] = {};

    issue(0, 0); CP_COMMIT();
    issue(1, 1); CP_COMMIT();
    issue(2, 2); CP_COMMIT();
    issue(3, 3); CP_COMMIT();

    int sc = 0, si = 4;
    for (int kt = 0; kt < KITERS; kt++) {
        CP_WAIT3();
        __syncthreads();
        if (kt + 4 < KITERS) issue(kt + 4, si);
        CP_COMMIT();

        const uint32_t ab = sbase + sc * STAGE_B;
        const uint32_t bb = ab + 10240;
        #pragma unroll
        for (int kk = 0; kk < 2; kk++) {
            uint32_t a[2][4];
            #pragma unroll
            for (int i = 0; i < 2; i++) {
                const uint32_t addr = ab + (wm * 32 + i * 16 + lrow) * 80 + (kk * 16 + lcol * 8) * 2;
                LDSM_X4(a[i][0], a[i][1], a[i][2], a[i][3], addr);
            }
            uint32_t b[8][2];
            #pragma unroll
            for (int j4 = 0; j4 < 4; j4++) {
                uint32_t q0, q1, q2, q3;
                const uint32_t addr = bb + (wn * 64 + j4 * 16 + lrow) * 80 + (kk * 16 + lcol * 8) * 2;
                LDSM_X4(q0, q1, q2, q3, addr);
                b[2 * j4][0] = q0;     b[2 * j4][1] = q2;
                b[2 * j4 + 1][0] = q1; b[2 * j4 + 1][1] = q3;
            }
            #pragma unroll
            for (int i = 0; i < 2; i++)
                #pragma unroll
                for (int j = 0; j < 8; j++)
                    MMA_F16(acc[i][j], a[i], b[j]);
        }
        sc = (sc + 1 == NSTAGE) ? 0 : sc + 1;
        si = (si + 1 == NSTAGE) ? 0 : si + 1;
    }

    const int rbase = tileM * 128 + wm * 32 + (lane >> 2);
    const int cbase = tileN * 128 + wn * 64 + (lane & 3) * 2;
    static const int roff[4] = {0, 8, 16, 24};

    const bool df_store = (mode == 3) && (tileN >= 16 && tileN < 24);
    if (mode == 1 || df_store) {
        unsigned* C16 = (unsigned*)Cv;
        const int ldu = ldc >> 1;
        const int creb = df_store ? 2048 : 0;
        #pragma unroll
        for (int j = 0; j < 8; j++) {
            const int col = cbase + j * 8;
            const float2 bz = *reinterpret_cast<const float2*>(bias + col);
            const int cl = col - creb;
            #pragma unroll
            for (int i = 0; i < 2; i++) {
                const int ra = rbase + i * 16;
                C16[(size_t)ra * ldu + (cl >> 1)] =
                    pack2(fmaxf(acc[i][j][0] + bz.x, 0.f), fmaxf(acc[i][j][1] + bz.y, 0.f));
                C16[(size_t)(ra + 8) * ldu + (cl >> 1)] =
                    pack2(fmaxf(acc[i][j][2] + bz.x, 0.f), fmaxf(acc[i][j][3] + bz.y, 0.f));
            }
        }
    } else if (mode == 3) {
        int nOut, lgoff, creg;
        const float* W2;
        if (tileN < 8)       { nOut = 7; W2 = Wc2; lgoff = 0; creg = 0; }
        else if (tileN < 16) { nOut = 1; W2 = Wr2; lgoff = 7; creg = 1024; }
        else                 { nOut = 6; W2 = Wo2; lgoff = 8; creg = 3072; }
        float s[4][7];
        #pragma unroll
        for (int rp = 0; rp < 4; rp++)
            #pragma unroll
            for (int c = 0; c < 7; c++) s[rp][c] = 0.f;
        #pragma unroll
        for (int j = 0; j < 8; j++) {
            const int col = cbase + j * 8;
            const float2 bz = *reinterpret_cast<const float2*>(bias + col);
            const int cl = col - creg;
            #pragma unroll
            for (int c = 0; c < 7; c++) {
                if (c < nOut) {
                    const float w0 = W2[(size_t)cl * nOut + c];
                    const float w1 = W2[(size_t)(cl + 1) * nOut + c];
                    #pragma unroll
                    for (int i = 0; i < 2; i++) {
                        const float v0 = fmaxf(acc[i][j][0] + bz.x, 0.f);
                        const float v1 = fmaxf(acc[i][j][1] + bz.y, 0.f);
                        const float v2 = fmaxf(acc[i][j][2] + bz.x, 0.f);
                        const float v3 = fmaxf(acc[i][j][3] + bz.y, 0.f);
                        s[i * 2 + 0][c] += v0 * w0 + v1 * w1;
                        s[i * 2 + 1][c] += v2 * w0 + v3 * w1;
                    }
                }
            }
        }
        #pragma unroll
        for (int off = 1; off <= 2; off <<= 1)
            #pragma unroll
            for (int rp = 0; rp < 4; rp++)
                #pragma unroll
                for (int c = 0; c < 7; c++)
                    s[rp][c] += __shfl_xor_sync(0xffffffffu, s[rp][c], off);
        if ((lane & 3) == 0) {
            #pragma unroll
            for (int rp = 0; rp < 4; rp++) {
                const int row = rbase + roff[rp];
                #pragma unroll
                for (int c = 0; c < 7; c++)
                    if (c < nOut) atomicAdd(&Lg[(size_t)row * 16 + lgoff + c], s[rp][c]);
            }
        }
    } else {
        const float* w3 = We3 + (size_t)e * D_DIM * 3;
        float s[4][3] = {};
        #pragma unroll
        for (int j = 0; j < 8; j++) {
            const int col = cbase + j * 8;
            const float2 bz = *reinterpret_cast<const float2*>(bias + col);
            const float w00 = w3[col * 3 + 0], w01 = w3[col * 3 + 1], w02 = w3[col * 3 + 2];
            const float w10 = w3[col * 3 + 3], w11 = w3[col * 3 + 4], w12 = w3[col * 3 + 5];
            #pragma unroll
            for (int i = 0; i < 2; i++) {
                const float v0 = fmaxf(acc[i][j][0] + bz.x, 0.f);
                const float v1 = fmaxf(acc[i][j][1] + bz.y, 0.f);
                const float v2 = fmaxf(acc[i][j][2] + bz.x, 0.f);
                const float v3 = fmaxf(acc[i][j][3] + bz.y, 0.f);
                s[i * 2 + 0][0] += v0 * w00 + v1 * w10;
                s[i * 2 + 0][1] += v0 * w01 + v1 * w11;
                s[i * 2 + 0][2] += v0 * w02 + v1 * w12;
                s[i * 2 + 1][0] += v2 * w00 + v3 * w10;
                s[i * 2 + 1][1] += v2 * w01 + v3 * w11;
                s[i * 2 + 1][2] += v2 * w02 + v3 * w12;
            }
        }
        #pragma unroll
        for (int off = 1; off <= 2; off <<= 1)
            #pragma unroll
            for (int rp = 0; rp < 4; rp++)
                #pragma unroll
                for (int t = 0; t < 3; t++)
                    s[rp][t] += __shfl_xor_sync(0xffffffffu, s[rp][t], off);
        if ((lane & 3) == 0) {
            float* out = (float*)Cv;
            #pragma unroll
            for (int rp = 0; rp < 4; rp++) {
                const int slot = rbase + roff[rp];
                const int p = d_perm[slot];
                if (p >= 0) {
                    atomicAdd(&out[(size_t)p * 24 + 21], s[rp][0]);
                    atomicAdd(&out[(size_t)p * 24 + 22], s[rp][1]);
                    atomicAdd(&out[(size_t)p * 24 + 23], s[rp][2]);
                }
            }
        }
    }
}

// ---------------- head finalize (1 thread/row) ----------------
__global__ void head2_kernel(const float* __restrict__ Lg,
                             const float* __restrict__ bc2, const float* __restrict__ bo2,
                             const float* __restrict__ br2, const float* __restrict__ be3,
                             float* __restrict__ out)
{
    const int row = blockIdx.x * blockDim.x + threadIdx.x;
    if (row >= B_ROWS) return;
    const float* lg = Lg + (size_t)row * 16;

    float sl[7];
    #pragma unroll
    for (int c = 0; c < 7; c++) sl[c] = lg[c] + bc2[c];
    float mx = sl[0];
    #pragma unroll
    for (int c = 1; c < 7; c++) mx = fmaxf(mx, sl[c]);
    float ex[7], ssum = 0.f;
    #pragma unroll
    for (int c = 0; c < 7; c++) { ex[c] = expf(sl[c] - mx); ssum += ex[c]; }
    const float inv = 1.f / ssum;

    float expected = 0.f;
    int idx = 0; float best = sl[0], best2 = -1e30f;
    float* orow = out + (size_t)row * 24;
    #pragma unroll
    for (int c = 0; c < 7; c++) {
        const float p = ex[c] * inv;
        expected = fmaf(p, (float)c * (1.0f / 6.0f), expected);
        orow[c] = sl[c];
        orow[14 + c] = p;
        if (c > 0) {
            if (sl[c] > best) { best2 = best; best = sl[c]; idx = c; }
            else if (sl[c] > best2) best2 = sl[c];
        }
    }
    #pragma unroll
    for (int c = 0; c < 6; c++) orow[7 + c] = lg[8 + c] + bo2[c];
    const float resid = 0.35f * tanhf(lg[7] + br2[0]);
    orow[13] = fminf(fmaxf(expected + resid, 0.f), 1.f);
    orow[21] = be3[idx * 3 + 0];
    orow[22] = be3[idx * 3 + 1];
    orow[23] = be3[idx * 3 + 2];
    d_size_idx[row] = idx;
    atomicAdd(&d_count[idx], 1);
    if (best - best2 < 4e-3f) {
        int p = atomicAdd(&d_fix_count, 1);
        if (p < B_ROWS) d_fix_rows[p] = row;
    }
}

// exact fp32 argmax recompute for near-tie rows
__global__ void fix_kernel(const float* __restrict__ x,
                           const float* __restrict__ Wc1, const float* __restrict__ bc1,
                           const float* __restrict__ Wc2, const float* __restrict__ bc2,
                           const float* __restrict__ be3,
                           float* __restrict__ out)
{
    __shared__ float xr[D_DIM];
    __shared__ float h[D_DIM];
    __shared__ float lg[8];
    int n = d_fix_count; if (n > B_ROWS) n = B_ROWS;
    for (int i = blockIdx.x; i < n; i += gridDim.x) {
        const int row = d_fix_rows[i];
        for (int k = threadIdx.x; k < D_DIM; k += 256) xr[k] = x[(size_t)row * D_DIM + k];
        __syncthreads();
        for (int j = threadIdx.x; j < D_DIM; j += 256) {
            float s = bc1[j];
            for (int k = 0; k < D_DIM; k++) s = fmaf(xr[k], Wc1[(size_t)k * D_DIM + j], s);
            h[j] = fmaxf(s, 0.f);
        }
        __syncthreads();
        const int w = threadIdx.x >> 5, l = threadIdx.x & 31;
        if (w < 7) {
            float s = 0.f;
            for (int k = l; k < D_DIM; k += 32) s = fmaf(h[k], Wc2[k * 7 + w], s);
            #pragma unroll
            for (int off = 16; off; off >>= 1) s += __shfl_xor_sync(0xffffffffu, s, off);
            if (!l) lg[w] = s + bc2[w];
        }
        __syncthreads();
        if (threadIdx.x == 0) {
            int idx = 0; float best = lg[0];
            #pragma unroll
            for (int c = 1; c < 7; c++) if (lg[c] > best) { best = lg[c]; idx = c; }
            const int old = d_size_idx[row];
            if (idx != old) {
                atomicSub(&d_count[old], 1);
                atomicAdd(&d_count[idx], 1);
                d_size_idx[row] = idx;
                float* orow = out + (size_t)row * 24;
                orow[21] = be3[idx * 3 + 0];
                orow[22] = be3[idx * 3 + 1];
                orow[23] = be3[idx * 3 + 2];
            }
        }
        __syncthreads();
    }
}

// ---------------- routing scan + scatter ----------------
__global__ void scan_kernel()
{
    int off = 0;
    for (int e = 0; e < N_EXP; e++) {
        d_off[e] = off;
        const int tiles = (d_count[e] + 127) >> 7;
        const int base = off >> 7;
        for (int t = 0; t < tiles; t++) d_tile_expert[base + t] = e;
        off += tiles << 7;
    }
}
__global__ void scatter_kernel()
{
    const int r = blockIdx.x * blockDim.x + threadIdx.x;
    if (r < B_ROWS) {
        const int e = d_size_idx[r];
        const int pos = d_off[e] + atomicAdd(&d_cursor[e], 1);
        d_perm[pos] = r;
    }
}

// ---------------- launch ----------------
extern "C" void kernel_launch(void* const* d_in, const int* in_sizes, int n_in,
                              void* d_out, int out_size)
{
    const float* x   = (const float*)d_in[0];
    const float* Wc1 = (const float*)d_in[1];
    const float* bc1 = (const float*)d_in[2];
    const float* Wc2 = (const float*)d_in[3];
    const float* bc2 = (const float*)d_in[4];
    const float* Wo1 = (const float*)d_in[5];
    const float* bo1 = (const float*)d_in[6];
    const float* Wo2 = (const float*)d_in[7];
    const float* bo2 = (const float*)d_in[8];
    const float* Wr1 = (const float*)d_in[9];
    const float* br1 = (const float*)d_in[10];
    const float* Wr2 = (const float*)d_in[11];
    const float* br2 = (const float*)d_in[12];
    const float* Wa  = (const float*)d_in[13];
    const float* ba  = (const float*)d_in[14];
    const float* We1 = (const float*)d_in[15];
    const float* be1 = (const float*)d_in[16];
    const float* We2 = (const float*)d_in[17];
    const float* be2 = (const float*)d_in[18];
    const float* We3 = (const float*)d_in[19];
    const float* be3 = (const float*)d_in[20];
    float* out = (float*)d_out;

    float* buf = nullptr;
    cudaGetSymbolAddress((void**)&buf, g_buf);
    __half*   Dfh  = (__half*)(buf + OFF_DFH);
    unsigned* X2   = (unsigned*)(buf + OFF_X2);
    unsigned* H12  = (unsigned*)(buf + OFF_H12);
    unsigned* Wcat = (unsigned*)(buf + OFF_WCAT);
    unsigned* W2e1 = (unsigned*)(buf + OFF_WE1);
    unsigned* W2e2 = (unsigned*)(buf + OFF_WE2);
    float*    bcat = buf + OFF_BCAT;
    float*    Lg   = buf + OFF_LG;

    cudaFuncSetAttribute(gemm_hmma, cudaFuncAttributeMaxDynamicSharedMemorySize, GSMEM_SZ);

    // 1-3: conversions (+fused init); gemm1 stays at launch #4 for ncu visibility
    conv_x_init_kernel<<<B_ROWS, 256>>>(x, (uint2*)X2, bc1, br1, ba, bo1, bcat, Lg);
    conv_wcat_kernel<<<dim3(16, 112), dim3(32, 8)>>>(Wc1, Wr1, Wa, Wo1, Wcat);
    conv_we_kernel<<<dim3(16, 32, 2 * N_EXP), dim3(32, 8)>>>(We1, We2, W2e1, W2e2);

    // 4: fused stage-1 GEMM: head dots -> Lg (atomics), Df -> fp16 Dfh
    gemm_hmma<<<dim3(NCAT / 128, B_ROWS / 128), 256, GSMEM_SZ>>>(
        (const __half*)X2, (const __half*)Wcat, bcat, Dfh, D_DIM, KDIM,
        0, 0, 0, 3, 0, nullptr, Wc2, Wr2, Wo2, Lg);

    // 5-8: head finalize + near-tie fixup + routing tables
    head2_kernel<<<(B_ROWS + 255) / 256, 256>>>(Lg, bc2, bo2, br2, be3, out);
    fix_kernel<<<64, 256>>>(x, Wc1, bc1, Wc2, bc2, be3, out);
    scan_kernel<<<1, 1>>>();
    scatter_kernel<<<(B_ROWS + 255) / 256, 256>>>();

    // 9-10: expert MLP (gemm2 gathers rows from dense Dfh; gemm3 depth-fused)
    gemm_hmma<<<dim3(8, MAX_TILES), 256, GSMEM_SZ>>>(
        (const __half*)Dfh, (const __half*)W2e1, be1, H12, D_DIM, D_DIM,
        1, (long long)D_DIM * KDIM, D_DIM, 1, 1, nullptr, nullptr, nullptr, nullptr, nullptr);
    gemm_hmma<<<dim3(8, MAX_TILES), 256, GSMEM_SZ>>>(
        (const __half*)H12, (const __half*)W2e2, be2, out, 24, KDIM,
        1, (long long)D_DIM * KDIM, D_DIM, 2, 0, We3, nullptr, nullptr, nullptr, nullptr);
}